// round 1
// baseline (speedup 1.0000x reference)
#include <cuda_runtime.h>
#include <math.h>

#define BATCH   2
#define S_LEN   2048
#define DMODEL  1024
#define NHEAD   16
#define HDIM    64
#define MROWS   (BATCH * S_LEN)   // 4096

// ---------------- scratch (allocation-free) ----------------
__device__ float g_q[MROWS * DMODEL];
__device__ float g_k[MROWS * DMODEL];
__device__ float g_v[MROWS * DMODEL];
__device__ float g_ctx[MROWS * DMODEL];

// ---------------- 128x128x8 SGEMM, 256 threads, 8x8 per thread ----------------
// C[M,N] = A[M,K] @ B[K,N] (+ bias[N] if bias != nullptr)
__global__ __launch_bounds__(256) void sgemm128(
    const float* __restrict__ A, const float* __restrict__ Bm,
    float* __restrict__ C, const float* __restrict__ bias,
    int M, int N, int K)
{
    __shared__ float As[8][128];
    __shared__ float Bs[8][128];

    const int tid  = threadIdx.x;
    const int bm   = blockIdx.y;
    const int bn   = blockIdx.x;
    const int tRow = tid >> 4;         // 0..15
    const int tCol = tid & 15;         // 0..15
    const int r0   = tRow * 4;         // rows r0..r0+3 and r0+64..r0+67
    const int c0   = tCol * 4;         // cols c0..c0+3 and c0+64..c0+67

    const int aRow = tid >> 1;         // 0..127
    const int aCol = (tid & 1) * 4;    // 0 or 4
    const int bRow = tid >> 5;         // 0..7
    const int bCol = (tid & 31) * 4;   // 0..124

    const float* Ab = A  + (size_t)(bm * 128) * K;
    const float* Bb = Bm + bn * 128;

    float acc[8][8];
#pragma unroll
    for (int i = 0; i < 8; i++)
#pragma unroll
        for (int j = 0; j < 8; j++) acc[i][j] = 0.0f;

    for (int k0 = 0; k0 < K; k0 += 8) {
        float4 av = *(const float4*)(Ab + (size_t)aRow * K + k0 + aCol);
        As[aCol + 0][aRow] = av.x;
        As[aCol + 1][aRow] = av.y;
        As[aCol + 2][aRow] = av.z;
        As[aCol + 3][aRow] = av.w;
        *(float4*)(&Bs[bRow][bCol]) =
            *(const float4*)(Bb + (size_t)(k0 + bRow) * N + bCol);
        __syncthreads();

#pragma unroll
        for (int kk = 0; kk < 8; kk++) {
            float rm[8], rn[8];
            *(float4*)&rm[0] = *(const float4*)&As[kk][r0];
            *(float4*)&rm[4] = *(const float4*)&As[kk][r0 + 64];
            *(float4*)&rn[0] = *(const float4*)&Bs[kk][c0];
            *(float4*)&rn[4] = *(const float4*)&Bs[kk][c0 + 64];
#pragma unroll
            for (int i = 0; i < 8; i++)
#pragma unroll
                for (int j = 0; j < 8; j++)
                    acc[i][j] = fmaf(rm[i], rn[j], acc[i][j]);
        }
        __syncthreads();
    }

    // epilogue
#pragma unroll
    for (int i = 0; i < 8; i++) {
        const int gr = bm * 128 + ((i < 4) ? (r0 + i) : (r0 + 64 + i - 4));
        float* Crow = C + (size_t)gr * N + bn * 128;
#pragma unroll
        for (int half = 0; half < 2; half++) {
            const int cc = c0 + half * 64;
            float4 out;
            out.x = acc[i][half * 4 + 0];
            out.y = acc[i][half * 4 + 1];
            out.z = acc[i][half * 4 + 2];
            out.w = acc[i][half * 4 + 3];
            if (bias != nullptr) {
                const float* bb = bias + bn * 128 + cc;
                out.x += bb[0]; out.y += bb[1]; out.z += bb[2]; out.w += bb[3];
            }
            *(float4*)(Crow + cc) = out;
        }
    }
}

// ---------------- flash attention (causal, unscaled) ----------------
// grid: (S/64, B*H), 256 threads. Each CTA: one 64-row q tile of one head.
// smem: Qt (transposed), Kt (transposed, reused as P), Vs. 3*16KB = 48KB.
__global__ __launch_bounds__(256) void flash_attn(
    const float* __restrict__ Q, const float* __restrict__ K,
    const float* __restrict__ V, float* __restrict__ Ctx)
{
    __shared__ float Qt[64][64];   // Qt[d][i]
    __shared__ float Kt[64][64];   // Kt[d][j]; reused as P[i][j]
    __shared__ float Vs[64][64];   // Vs[j][c]

    const int tid   = threadIdx.x;
    const int qtile = blockIdx.x;              // 0..31
    const int bh    = blockIdx.y;              // 0..31
    const int b     = bh / NHEAD;
    const int h     = bh % NHEAD;
    const int tx    = tid & 15;                // col group
    const int ty    = tid >> 4;                // row group

    const size_t base = ((size_t)b * S_LEN) * DMODEL + (size_t)h * HDIM;

    // load Q tile, transposed
#pragma unroll
    for (int it = 0; it < 4; it++) {
        int idx = tid + it * 256;              // float4 index over 64x16
        int row = idx >> 4;
        int c4  = (idx & 15) << 2;
        float4 v = *(const float4*)(Q + base + (size_t)(qtile * 64 + row) * DMODEL + c4);
        Qt[c4 + 0][row] = v.x;
        Qt[c4 + 1][row] = v.y;
        Qt[c4 + 2][row] = v.z;
        Qt[c4 + 3][row] = v.w;
    }

    float o[4][4];
#pragma unroll
    for (int i = 0; i < 4; i++)
#pragma unroll
        for (int j = 0; j < 4; j++) o[i][j] = 0.0f;
    float m_i[4] = {-3.0e38f, -3.0e38f, -3.0e38f, -3.0e38f};
    float l_i[4] = {0.0f, 0.0f, 0.0f, 0.0f};

    const int ktiles = qtile + 1;              // causal
    for (int kt = 0; kt < ktiles; kt++) {
        __syncthreads();                        // prior iter done with Kt(P)/Vs
        // load K (transposed) and V tiles
#pragma unroll
        for (int it = 0; it < 4; it++) {
            int idx = tid + it * 256;
            int row = idx >> 4;
            int c4  = (idx & 15) << 2;
            const size_t goff = base + (size_t)(kt * 64 + row) * DMODEL + c4;
            float4 kv = *(const float4*)(K + goff);
            Kt[c4 + 0][row] = kv.x;
            Kt[c4 + 1][row] = kv.y;
            Kt[c4 + 2][row] = kv.z;
            Kt[c4 + 3][row] = kv.w;
            *(float4*)(&Vs[row][c4]) = *(const float4*)(V + goff);
        }
        __syncthreads();

        // S = Q @ K^T  (4x4 fragment)
        float s[4][4];
#pragma unroll
        for (int i = 0; i < 4; i++)
#pragma unroll
            for (int j = 0; j < 4; j++) s[i][j] = 0.0f;
#pragma unroll 8
        for (int d = 0; d < 64; d++) {
            float4 qv = *(const float4*)&Qt[d][ty * 4];
            float4 kv = *(const float4*)&Kt[d][tx * 4];
            float qf[4] = {qv.x, qv.y, qv.z, qv.w};
            float kf[4] = {kv.x, kv.y, kv.z, kv.w};
#pragma unroll
            for (int i = 0; i < 4; i++)
#pragma unroll
                for (int j = 0; j < 4; j++)
                    s[i][j] = fmaf(qf[i], kf[j], s[i][j]);
        }

        // causal mask (diag tile only): kv_index > q_index -> -inf
        if (kt == qtile) {
#pragma unroll
            for (int i = 0; i < 4; i++)
#pragma unroll
                for (int j = 0; j < 4; j++)
                    if (tx * 4 + j > ty * 4 + i) s[i][j] = -3.0e38f;
        }

        // row max (across jj then across the 16 tx lanes)
        float p[4][4], rs[4], scale[4];
#pragma unroll
        for (int i = 0; i < 4; i++) {
            float mx = fmaxf(fmaxf(s[i][0], s[i][1]), fmaxf(s[i][2], s[i][3]));
            mx = fmaxf(mx, __shfl_xor_sync(0xffffffffu, mx, 1));
            mx = fmaxf(mx, __shfl_xor_sync(0xffffffffu, mx, 2));
            mx = fmaxf(mx, __shfl_xor_sync(0xffffffffu, mx, 4));
            mx = fmaxf(mx, __shfl_xor_sync(0xffffffffu, mx, 8));
            float m_new = fmaxf(m_i[i], mx);
            scale[i] = __expf(m_i[i] - m_new);   // m_i=-3e38 -> 0
            float r = 0.0f;
#pragma unroll
            for (int j = 0; j < 4; j++) {
                p[i][j] = __expf(s[i][j] - m_new);
                r += p[i][j];
            }
            r += __shfl_xor_sync(0xffffffffu, r, 1);
            r += __shfl_xor_sync(0xffffffffu, r, 2);
            r += __shfl_xor_sync(0xffffffffu, r, 4);
            r += __shfl_xor_sync(0xffffffffu, r, 8);
            rs[i]  = r;
            m_i[i] = m_new;
            l_i[i] = l_i[i] * scale[i] + rs[i];
#pragma unroll
            for (int j = 0; j < 4; j++) o[i][j] *= scale[i];
        }

        __syncthreads();                        // all reads of Kt done
        // write P into Kt buffer as P[i][j]
#pragma unroll
        for (int i = 0; i < 4; i++) {
            float4 pv;
            pv.x = p[i][0]; pv.y = p[i][1]; pv.z = p[i][2]; pv.w = p[i][3];
            *(float4*)(&Kt[ty * 4 + i][tx * 4]) = pv;
        }
        __syncthreads();

        // O += P @ V
#pragma unroll 8
        for (int j = 0; j < 64; j++) {
            float4 vv = *(const float4*)&Vs[j][tx * 4];
#pragma unroll
            for (int i = 0; i < 4; i++) {
                float pv = Kt[ty * 4 + i][j];
                o[i][0] = fmaf(pv, vv.x, o[i][0]);
                o[i][1] = fmaf(pv, vv.y, o[i][1]);
                o[i][2] = fmaf(pv, vv.z, o[i][2]);
                o[i][3] = fmaf(pv, vv.w, o[i][3]);
            }
        }
    }

    // normalize + write ctx[b, q, h*64 + c]
#pragma unroll
    for (int i = 0; i < 4; i++) {
        const float inv = 1.0f / l_i[i];
        const int gq = qtile * 64 + ty * 4 + i;
        float4 ov;
        ov.x = o[i][0] * inv; ov.y = o[i][1] * inv;
        ov.z = o[i][2] * inv; ov.w = o[i][3] * inv;
        *(float4*)(Ctx + base + (size_t)gq * DMODEL + tx * 4) = ov;
    }
}

// ---------------- launcher ----------------
extern "C" void kernel_launch(void* const* d_in, const int* in_sizes, int n_in,
                              void* d_out, int out_size)
{
    const float* X  = (const float*)d_in[0];
    const float* Wq = (const float*)d_in[1];
    const float* Wk = (const float*)d_in[2];
    const float* Wv = (const float*)d_in[3];
    const float* Wo = (const float*)d_in[4];
    const float* bo = (const float*)d_in[5];
    float* out = (float*)d_out;

    float *q, *k, *v, *ctx;
    cudaGetSymbolAddress((void**)&q,   g_q);
    cudaGetSymbolAddress((void**)&k,   g_k);
    cudaGetSymbolAddress((void**)&v,   g_v);
    cudaGetSymbolAddress((void**)&ctx, g_ctx);

    dim3 gGemm(DMODEL / 128, MROWS / 128);   // (8, 32)
    sgemm128<<<gGemm, 256>>>(X, Wq, q, nullptr, MROWS, DMODEL, DMODEL);
    sgemm128<<<gGemm, 256>>>(X, Wk, k, nullptr, MROWS, DMODEL, DMODEL);
    sgemm128<<<gGemm, 256>>>(X, Wv, v, nullptr, MROWS, DMODEL, DMODEL);

    dim3 gAttn(S_LEN / 64, BATCH * NHEAD);   // (32, 32)
    flash_attn<<<gAttn, 256>>>(q, k, v, ctx);

    sgemm128<<<gGemm, 256>>>(ctx, Wo, out, bo, MROWS, DMODEL, DMODEL);
}

// round 8
// speedup vs baseline: 1.4887x; 1.4887x over previous
#include <cuda_runtime.h>
#include <cuda_bf16.h>
#include <stdint.h>
#include <math.h>

#define BATCH   2
#define S_LEN   2048
#define DMODEL  1024
#define NHEAD   16
#define HDIM    64
#define MROWS   (BATCH * S_LEN)   // 4096
#define KBIG    (3 * DMODEL)      // 3072: A=[hi|lo|hi], B=[hi|hi|lo]
#define KCH     (KBIG / 64)       // 48 chunks of K=64

// ---------------- scratch (allocation-free device globals) ----------------
__device__ __align__(16) __nv_bfloat16 g_xbig[MROWS * KBIG];   // 24MB
__device__ __align__(16) __nv_bfloat16 g_cbig[MROWS * KBIG];   // 24MB
__device__ __align__(16) __nv_bfloat16 g_wqb[DMODEL * KBIG];   // 6MB each
__device__ __align__(16) __nv_bfloat16 g_wkb[DMODEL * KBIG];
__device__ __align__(16) __nv_bfloat16 g_wvb[DMODEL * KBIG];
__device__ __align__(16) __nv_bfloat16 g_wob[DMODEL * KBIG];
__device__ float g_q[MROWS * DMODEL];
__device__ float g_k[MROWS * DMODEL];
__device__ float g_v[MROWS * DMODEL];
__device__ float g_ctx[MROWS * DMODEL];

// ---------------- PTX helpers (all legal on plain sm_103) ----------------
__device__ __forceinline__ uint32_t smem_u32(const void* p) {
    uint32_t a;
    asm("{ .reg .u64 t; cvta.to.shared.u64 t, %1; cvt.u32.u64 %0, t; }" : "=r"(a) : "l"(p));
    return a;
}
__device__ __forceinline__ void cp_async16(uint32_t saddr, const void* gaddr) {
    asm volatile("cp.async.cg.shared.global [%0], [%1], 16;" :: "r"(saddr), "l"(gaddr));
}
__device__ __forceinline__ void cp_commit() {
    asm volatile("cp.async.commit_group;" ::: "memory");
}
__device__ __forceinline__ void cp_wait0() {
    asm volatile("cp.async.wait_group 0;" ::: "memory");
}
__device__ __forceinline__ void ldm_x4(uint32_t& r0, uint32_t& r1, uint32_t& r2, uint32_t& r3,
                                       uint32_t addr) {
    asm volatile("ldmatrix.sync.aligned.m8n8.x4.shared.b16 {%0,%1,%2,%3}, [%4];"
                 : "=r"(r0), "=r"(r1), "=r"(r2), "=r"(r3) : "r"(addr));
}
__device__ __forceinline__ void ldm_x2(uint32_t& r0, uint32_t& r1, uint32_t addr) {
    asm volatile("ldmatrix.sync.aligned.m8n8.x2.shared.b16 {%0,%1}, [%2];"
                 : "=r"(r0), "=r"(r1) : "r"(addr));
}
__device__ __forceinline__ void mma_bf16(float* d, const uint32_t* a, const uint32_t* b) {
    asm volatile(
        "mma.sync.aligned.m16n8k16.row.col.f32.bf16.bf16.f32 "
        "{%0,%1,%2,%3}, {%4,%5,%6,%7}, {%8,%9}, {%0,%1,%2,%3};"
        : "+f"(d[0]), "+f"(d[1]), "+f"(d[2]), "+f"(d[3])
        : "r"(a[0]), "r"(a[1]), "r"(a[2]), "r"(a[3]), "r"(b[0]), "r"(b[1]));
}

// ---------------- conversion: fp32 -> bf16 hi/lo packed, K'=3072 ----------------
// A segs: [hi | lo | hi]   (pairs with W segs [hi | hi | lo])
__global__ __launch_bounds__(256) void cvt_x(const float* __restrict__ X,
                                             __nv_bfloat16* __restrict__ O)
{
    int idx = blockIdx.x * 256 + threadIdx.x;      // one thread per 4 elems
    int m   = idx >> 8;                            // 256 quads per row
    int k4  = (idx & 255) << 2;
    float4 v = *(const float4*)(X + (size_t)m * DMODEL + k4);
    float f[4] = {v.x, v.y, v.z, v.w};
    __nv_bfloat16 h[4], l[4];
#pragma unroll
    for (int i = 0; i < 4; i++) {
        h[i] = __float2bfloat16(f[i]);
        l[i] = __float2bfloat16(f[i] - __bfloat162float(h[i]));
    }
    __nv_bfloat162 h01, h23, l01, l23;
    h01.x = h[0]; h01.y = h[1]; h23.x = h[2]; h23.y = h[3];
    l01.x = l[0]; l01.y = l[1]; l23.x = l[2]; l23.y = l[3];
    __nv_bfloat162* p0 = (__nv_bfloat162*)(O + (size_t)m * KBIG + k4);
    __nv_bfloat162* p1 = (__nv_bfloat162*)(O + (size_t)m * KBIG + DMODEL + k4);
    __nv_bfloat162* p2 = (__nv_bfloat162*)(O + (size_t)m * KBIG + 2 * DMODEL + k4);
    p0[0] = h01; p0[1] = h23;      // seg0: hi  (x hi * w hi)
    p1[0] = l01; p1[1] = l23;      // seg1: lo  (x lo * w hi)
    p2[0] = h01; p2[1] = h23;      // seg2: hi  (x hi * w lo)
}

// W[k][n] fp32 -> Wt[n][k'] bf16, segs [hi ; hi ; lo] (transposed, K-major)
__global__ __launch_bounds__(256) void cvt_w(const float* __restrict__ W,
                                             __nv_bfloat16* __restrict__ O)
{
    __shared__ float t[32][33];
    int n0 = blockIdx.x * 32, k0 = blockIdx.y * 32;
    int tx = threadIdx.x, ty = threadIdx.y;        // (32, 8)
#pragma unroll
    for (int i = 0; i < 4; i++)
        t[ty + 8 * i][tx] = W[(size_t)(k0 + ty + 8 * i) * DMODEL + n0 + tx];
    __syncthreads();
#pragma unroll
    for (int i = 0; i < 4; i++) {
        int n = n0 + ty + 8 * i, k = k0 + tx;
        float v = t[tx][ty + 8 * i];
        __nv_bfloat16 h = __float2bfloat16(v);
        __nv_bfloat16 l = __float2bfloat16(v - __bfloat162float(h));
        O[(size_t)n * KBIG + k]              = h;   // seg0: hi
        O[(size_t)n * KBIG + DMODEL + k]     = h;   // seg1: hi
        O[(size_t)n * KBIG + 2 * DMODEL + k] = l;   // seg2: lo
    }
}

// ---------------- bf16 HMMA GEMM: C[4096,1024] = Abig @ Bt^T ----------------
// Tiles: CTA 128x128, K chunk 64. 8 warps: warp tile 64x32 (wm = wid&1, wn = wid>>1).
// A row-major [M][K'], Bt K-major [N][K']. SW128 XOR swizzle, cp.async double buffer.
__global__ __launch_bounds__(256) void gemm_mma(
    const __nv_bfloat16* __restrict__ A,
    const __nv_bfloat16* __restrict__ B0, const __nv_bfloat16* __restrict__ B1,
    const __nv_bfloat16* __restrict__ B2,
    float* C0, float* C1, float* C2,
    const float* __restrict__ bias)
{
    extern __shared__ __align__(1024) unsigned char dsm[];

    const __nv_bfloat16* Bt = (blockIdx.z == 0) ? B0 : (blockIdx.z == 1) ? B1 : B2;
    float* C                = (blockIdx.z == 0) ? C0 : (blockIdx.z == 1) ? C1 : C2;

    const int tid  = threadIdx.x;
    const int wid  = tid >> 5;
    const int lane = tid & 31;
    const int bm   = blockIdx.y, bn = blockIdx.x;
    const int wm   = (wid & 1) * 64;     // warp M offset
    const int wn   = (wid >> 1) * 32;    // warp N offset

    const uint32_t s0 = smem_u32(dsm);
    const uint32_t sA = (s0 + 1023) & ~1023u;     // [2][128][64] bf16, 16KB/stage
    const uint32_t sB = sA + 32768;               // [2][128][64] bf16

    // ---- global->smem producer addressing (constant swizzle per thread) ----
    const int row0 = tid >> 3;                    // 0..31
    const int seg  = tid & 7;                     // 16B segment within 128B row
    const uint32_t swz = (uint32_t)((seg ^ (row0 & 7)) << 4);
    const __nv_bfloat16* aG = A  + (size_t)(bm * 128 + row0) * KBIG + seg * 8;
    const __nv_bfloat16* bG = Bt + (size_t)(bn * 128 + row0) * KBIG + seg * 8;
    const uint32_t stA = sA + row0 * 128 + swz;
    const uint32_t stB = sB + row0 * 128 + swz;

    // ---- consumer (ldmatrix) addressing ----
    uint32_t aBase[4], bBase[4], aMask[4], bMask[4];
#pragma unroll
    for (int mi = 0; mi < 4; mi++) {
        int r = wm + mi * 16 + (lane & 15);
        aBase[mi] = sA + r * 128;
        aMask[mi] = r & 7;
    }
#pragma unroll
    for (int ni = 0; ni < 4; ni++) {
        int r = wn + ni * 8 + (lane & 7);
        bBase[ni] = sB + r * 128;
        bMask[ni] = r & 7;
    }
    const uint32_t kselA = (lane >> 4);          // 0/1
    const uint32_t kselB = (lane >> 3) & 1;      // 0/1

    float acc[4][4][4];
#pragma unroll
    for (int mi = 0; mi < 4; mi++)
#pragma unroll
        for (int ni = 0; ni < 4; ni++)
#pragma unroll
            for (int r = 0; r < 4; r++) acc[mi][ni][r] = 0.0f;

    // ---- pipeline ----
    auto load_chunk = [&](int c, int buf) {
        const uint32_t bo = (uint32_t)buf * 16384;
        const __nv_bfloat16* ap = aG + c * 64;
        const __nv_bfloat16* bp = bG + c * 64;
#pragma unroll
        for (int i = 0; i < 4; i++) {
            cp_async16(stA + bo + i * 4096, ap + (size_t)i * 32 * KBIG);
            cp_async16(stB + bo + i * 4096, bp + (size_t)i * 32 * KBIG);
        }
        cp_commit();
    };

    load_chunk(0, 0);
    int buf = 0;
    for (int c = 0; c < KCH; c++) {
        cp_wait0();
        __syncthreads();
        if (c + 1 < KCH) load_chunk(c + 1, buf ^ 1);
        const uint32_t bo = (uint32_t)buf * 16384;
#pragma unroll
        for (int ks = 0; ks < 4; ks++) {
            uint32_t a[4][4], b[4][2];
#pragma unroll
            for (int mi = 0; mi < 4; mi++) {
                uint32_t u = (uint32_t)(ks * 2) + kselA;
                ldm_x4(a[mi][0], a[mi][1], a[mi][2], a[mi][3],
                       aBase[mi] + bo + ((u ^ aMask[mi]) << 4));
            }
#pragma unroll
            for (int ni = 0; ni < 4; ni++) {
                uint32_t u = (uint32_t)(ks * 2) + kselB;
                ldm_x2(b[ni][0], b[ni][1],
                       bBase[ni] + bo + ((u ^ bMask[ni]) << 4));
            }
#pragma unroll
            for (int mi = 0; mi < 4; mi++)
#pragma unroll
                for (int ni = 0; ni < 4; ni++)
                    mma_bf16(acc[mi][ni], a[mi], b[ni]);
        }
        buf ^= 1;
    }

    // ---- epilogue ----
    const int rbase = bm * 128 + wm + (lane >> 2);
    const int cbase = bn * 128 + wn + (lane & 3) * 2;
#pragma unroll
    for (int mi = 0; mi < 4; mi++) {
#pragma unroll
        for (int ni = 0; ni < 4; ni++) {
            const int col = cbase + ni * 8;
            float b0 = 0.0f, b1 = 0.0f;
            if (bias != nullptr) { b0 = bias[col]; b1 = bias[col + 1]; }
            float2 v01, v23;
            v01.x = acc[mi][ni][0] + b0; v01.y = acc[mi][ni][1] + b1;
            v23.x = acc[mi][ni][2] + b0; v23.y = acc[mi][ni][3] + b1;
            *(float2*)(C + (size_t)(rbase + mi * 16)     * DMODEL + col) = v01;
            *(float2*)(C + (size_t)(rbase + mi * 16 + 8) * DMODEL + col) = v23;
        }
    }
}

// ---------------- flash attention (verified R1 fp32 version) ----------------
__global__ __launch_bounds__(256) void flash_attn(
    const float* __restrict__ Q, const float* __restrict__ K,
    const float* __restrict__ V, float* __restrict__ Ctx)
{
    __shared__ float Qt[64][64];
    __shared__ float Kt[64][64];
    __shared__ float Vs[64][64];

    const int tid   = threadIdx.x;
    const int qtile = blockIdx.x;
    const int bh    = blockIdx.y;
    const int b     = bh / NHEAD;
    const int h     = bh % NHEAD;
    const int tx    = tid & 15;
    const int ty    = tid >> 4;

    const size_t base = ((size_t)b * S_LEN) * DMODEL + (size_t)h * HDIM;

#pragma unroll
    for (int it = 0; it < 4; it++) {
        int idx = tid + it * 256;
        int row = idx >> 4;
        int c4  = (idx & 15) << 2;
        float4 v = *(const float4*)(Q + base + (size_t)(qtile * 64 + row) * DMODEL + c4);
        Qt[c4 + 0][row] = v.x; Qt[c4 + 1][row] = v.y;
        Qt[c4 + 2][row] = v.z; Qt[c4 + 3][row] = v.w;
    }

    float o[4][4];
#pragma unroll
    for (int i = 0; i < 4; i++)
#pragma unroll
        for (int j = 0; j < 4; j++) o[i][j] = 0.0f;
    float m_i[4] = {-3.0e38f, -3.0e38f, -3.0e38f, -3.0e38f};
    float l_i[4] = {0.0f, 0.0f, 0.0f, 0.0f};

    const int ktiles = qtile + 1;
    for (int kt = 0; kt < ktiles; kt++) {
        __syncthreads();
#pragma unroll
        for (int it = 0; it < 4; it++) {
            int idx = tid + it * 256;
            int row = idx >> 4;
            int c4  = (idx & 15) << 2;
            const size_t goff = base + (size_t)(kt * 64 + row) * DMODEL + c4;
            float4 kv = *(const float4*)(K + goff);
            Kt[c4 + 0][row] = kv.x; Kt[c4 + 1][row] = kv.y;
            Kt[c4 + 2][row] = kv.z; Kt[c4 + 3][row] = kv.w;
            *(float4*)(&Vs[row][c4]) = *(const float4*)(V + goff);
        }
        __syncthreads();

        float s[4][4];
#pragma unroll
        for (int i = 0; i < 4; i++)
#pragma unroll
            for (int j = 0; j < 4; j++) s[i][j] = 0.0f;
#pragma unroll 8
        for (int d = 0; d < 64; d++) {
            float4 qv = *(const float4*)&Qt[d][ty * 4];
            float4 kv = *(const float4*)&Kt[d][tx * 4];
            float qf[4] = {qv.x, qv.y, qv.z, qv.w};
            float kf[4] = {kv.x, kv.y, kv.z, kv.w};
#pragma unroll
            for (int i = 0; i < 4; i++)
#pragma unroll
                for (int j = 0; j < 4; j++)
                    s[i][j] = fmaf(qf[i], kf[j], s[i][j]);
        }

        if (kt == qtile) {
#pragma unroll
            for (int i = 0; i < 4; i++)
#pragma unroll
                for (int j = 0; j < 4; j++)
                    if (tx * 4 + j > ty * 4 + i) s[i][j] = -3.0e38f;
        }

        float p[4][4];
#pragma unroll
        for (int i = 0; i < 4; i++) {
            float mx = fmaxf(fmaxf(s[i][0], s[i][1]), fmaxf(s[i][2], s[i][3]));
            mx = fmaxf(mx, __shfl_xor_sync(0xffffffffu, mx, 1));
            mx = fmaxf(mx, __shfl_xor_sync(0xffffffffu, mx, 2));
            mx = fmaxf(mx, __shfl_xor_sync(0xffffffffu, mx, 4));
            mx = fmaxf(mx, __shfl_xor_sync(0xffffffffu, mx, 8));
            float m_new = fmaxf(m_i[i], mx);
            float scale = __expf(m_i[i] - m_new);
            float r = 0.0f;
#pragma unroll
            for (int j = 0; j < 4; j++) { p[i][j] = __expf(s[i][j] - m_new); r += p[i][j]; }
            r += __shfl_xor_sync(0xffffffffu, r, 1);
            r += __shfl_xor_sync(0xffffffffu, r, 2);
            r += __shfl_xor_sync(0xffffffffu, r, 4);
            r += __shfl_xor_sync(0xffffffffu, r, 8);
            m_i[i] = m_new;
            l_i[i] = l_i[i] * scale + r;
#pragma unroll
            for (int j = 0; j < 4; j++) o[i][j] *= scale;
        }

        __syncthreads();
#pragma unroll
        for (int i = 0; i < 4; i++) {
            float4 pv;
            pv.x = p[i][0]; pv.y = p[i][1]; pv.z = p[i][2]; pv.w = p[i][3];
            *(float4*)(&Kt[ty * 4 + i][tx * 4]) = pv;
        }
        __syncthreads();

#pragma unroll 8
        for (int j = 0; j < 64; j++) {
            float4 vv = *(const float4*)&Vs[j][tx * 4];
#pragma unroll
            for (int i = 0; i < 4; i++) {
                float pv = Kt[ty * 4 + i][j];
                o[i][0] = fmaf(pv, vv.x, o[i][0]);
                o[i][1] = fmaf(pv, vv.y, o[i][1]);
                o[i][2] = fmaf(pv, vv.z, o[i][2]);
                o[i][3] = fmaf(pv, vv.w, o[i][3]);
            }
        }
    }

#pragma unroll
    for (int i = 0; i < 4; i++) {
        const float inv = 1.0f / l_i[i];
        const int gq = qtile * 64 + ty * 4 + i;
        float4 ov;
        ov.x = o[i][0] * inv; ov.y = o[i][1] * inv;
        ov.z = o[i][2] * inv; ov.w = o[i][3] * inv;
        *(float4*)(Ctx + base + (size_t)gq * DMODEL + tx * 4) = ov;
    }
}

// ---------------- launcher ----------------
extern "C" void kernel_launch(void* const* d_in, const int* in_sizes, int n_in,
                              void* d_out, int out_size)
{
    const float* X  = (const float*)d_in[0];
    const float* Wq = (const float*)d_in[1];
    const float* Wk = (const float*)d_in[2];
    const float* Wv = (const float*)d_in[3];
    const float* Wo = (const float*)d_in[4];
    const float* bo = (const float*)d_in[5];
    float* out = (float*)d_out;

    __nv_bfloat16 *xbig, *cbig, *wqb, *wkb, *wvb, *wob;
    float *q, *k, *v, *ctx;
    cudaGetSymbolAddress((void**)&xbig, g_xbig);
    cudaGetSymbolAddress((void**)&cbig, g_cbig);
    cudaGetSymbolAddress((void**)&wqb,  g_wqb);
    cudaGetSymbolAddress((void**)&wkb,  g_wkb);
    cudaGetSymbolAddress((void**)&wvb,  g_wvb);
    cudaGetSymbolAddress((void**)&wob,  g_wob);
    cudaGetSymbolAddress((void**)&q,    g_q);
    cudaGetSymbolAddress((void**)&k,    g_k);
    cudaGetSymbolAddress((void**)&v,    g_v);
    cudaGetSymbolAddress((void**)&ctx,  g_ctx);

    const int SMEM_DYN = 65536 + 1024;
    cudaFuncSetAttribute(gemm_mma, cudaFuncAttributeMaxDynamicSharedMemorySize, SMEM_DYN);

    // input / weight conversion to bf16 hi-lo split
    cvt_x<<<MROWS * DMODEL / (256 * 4), 256>>>(X, xbig);
    dim3 wgrid(DMODEL / 32, DMODEL / 32);
    cvt_w<<<wgrid, dim3(32, 8)>>>(Wq, wqb);
    cvt_w<<<wgrid, dim3(32, 8)>>>(Wk, wkb);
    cvt_w<<<wgrid, dim3(32, 8)>>>(Wv, wvb);
    cvt_w<<<wgrid, dim3(32, 8)>>>(Wo, wob);

    // fused QKV projection on tensor cores (HMMA)
    gemm_mma<<<dim3(DMODEL / 128, MROWS / 128, 3), 256, SMEM_DYN>>>(
        xbig, wqb, wkb, wvb, q, k, v, nullptr);

    // attention (fp32, unchanged)
    flash_attn<<<dim3(S_LEN / 64, BATCH * NHEAD), 256>>>(q, k, v, ctx);

    // output projection
    cvt_x<<<MROWS * DMODEL / (256 * 4), 256>>>(ctx, cbig);
    gemm_mma<<<dim3(DMODEL / 128, MROWS / 128, 1), 256, SMEM_DYN>>>(
        cbig, wob, wob, wob, out, out, out, bo);
}

// round 9
// speedup vs baseline: 3.0367x; 2.0398x over previous
#include <cuda_runtime.h>
#include <cuda_bf16.h>
#include <stdint.h>
#include <math.h>

#define BATCH   2
#define S_LEN   2048
#define DMODEL  1024
#define NHEAD   16
#define HDIM    64
#define MROWS   (BATCH * S_LEN)   // 4096
#define KBIG    (3 * DMODEL)      // 3072: A=[hi|lo|hi], B=[hi|hi|lo]
#define KCH     (KBIG / 64)       // 48 chunks of K=64
#define NBH     (BATCH * NHEAD)   // 32

// ---------------- scratch (allocation-free device globals) ----------------
__device__ __align__(16) __nv_bfloat16 g_xbig[MROWS * KBIG];   // 24MB
__device__ __align__(16) __nv_bfloat16 g_cbig[MROWS * KBIG];   // 24MB
__device__ __align__(16) __nv_bfloat16 g_wqb[DMODEL * KBIG];
__device__ __align__(16) __nv_bfloat16 g_wkb[DMODEL * KBIG];
__device__ __align__(16) __nv_bfloat16 g_wvb[DMODEL * KBIG];
__device__ __align__(16) __nv_bfloat16 g_wob[DMODEL * KBIG];
__device__ float g_q[MROWS * DMODEL];
__device__ float g_k[MROWS * DMODEL];
__device__ float g_v[MROWS * DMODEL];
__device__ float g_ctx[MROWS * DMODEL];
// attention bf16 hi/lo operands
__device__ __align__(16) __nv_bfloat16 g_qh[NBH * S_LEN * HDIM];   // 8MB each
__device__ __align__(16) __nv_bfloat16 g_ql[NBH * S_LEN * HDIM];
__device__ __align__(16) __nv_bfloat16 g_kh[NBH * S_LEN * HDIM];
__device__ __align__(16) __nv_bfloat16 g_kl[NBH * S_LEN * HDIM];
__device__ __align__(16) __nv_bfloat16 g_vth[NBH * HDIM * S_LEN];  // transposed
__device__ __align__(16) __nv_bfloat16 g_vtl[NBH * HDIM * S_LEN];

// ---------------- PTX helpers (all legal on plain sm_103) ----------------
__device__ __forceinline__ uint32_t smem_u32(const void* p) {
    uint32_t a;
    asm("{ .reg .u64 t; cvta.to.shared.u64 t, %1; cvt.u32.u64 %0, t; }" : "=r"(a) : "l"(p));
    return a;
}
__device__ __forceinline__ void cp_async16(uint32_t saddr, const void* gaddr) {
    asm volatile("cp.async.cg.shared.global [%0], [%1], 16;" :: "r"(saddr), "l"(gaddr));
}
__device__ __forceinline__ void cp_commit() {
    asm volatile("cp.async.commit_group;" ::: "memory");
}
__device__ __forceinline__ void cp_wait0() {
    asm volatile("cp.async.wait_group 0;" ::: "memory");
}
__device__ __forceinline__ void ldm_x4(uint32_t& r0, uint32_t& r1, uint32_t& r2, uint32_t& r3,
                                       uint32_t addr) {
    asm volatile("ldmatrix.sync.aligned.m8n8.x4.shared.b16 {%0,%1,%2,%3}, [%4];"
                 : "=r"(r0), "=r"(r1), "=r"(r2), "=r"(r3) : "r"(addr));
}
__device__ __forceinline__ void ldm_x2(uint32_t& r0, uint32_t& r1, uint32_t addr) {
    asm volatile("ldmatrix.sync.aligned.m8n8.x2.shared.b16 {%0,%1}, [%2];"
                 : "=r"(r0), "=r"(r1) : "r"(addr));
}
__device__ __forceinline__ void mma_bf16(float* d, const uint32_t* a, const uint32_t* b) {
    asm volatile(
        "mma.sync.aligned.m16n8k16.row.col.f32.bf16.bf16.f32 "
        "{%0,%1,%2,%3}, {%4,%5,%6,%7}, {%8,%9}, {%0,%1,%2,%3};"
        : "+f"(d[0]), "+f"(d[1]), "+f"(d[2]), "+f"(d[3])
        : "r"(a[0]), "r"(a[1]), "r"(a[2]), "r"(a[3]), "r"(b[0]), "r"(b[1]));
}
__device__ __forceinline__ uint32_t packbf2(float a, float b) {
    __nv_bfloat162 t = __floats2bfloat162_rn(a, b);
    return *reinterpret_cast<uint32_t*>(&t);
}
__device__ __forceinline__ float bf16rt(float v) {
    return __bfloat162float(__float2bfloat16(v));
}

// ---------------- conversion: fp32 -> bf16 hi/lo packed, K'=3072 ----------------
__global__ __launch_bounds__(256) void cvt_x(const float* __restrict__ X,
                                             __nv_bfloat16* __restrict__ O)
{
    int idx = blockIdx.x * 256 + threadIdx.x;
    int m   = idx >> 8;
    int k4  = (idx & 255) << 2;
    float4 v = *(const float4*)(X + (size_t)m * DMODEL + k4);
    float f[4] = {v.x, v.y, v.z, v.w};
    __nv_bfloat16 h[4], l[4];
#pragma unroll
    for (int i = 0; i < 4; i++) {
        h[i] = __float2bfloat16(f[i]);
        l[i] = __float2bfloat16(f[i] - __bfloat162float(h[i]));
    }
    __nv_bfloat162 h01, h23, l01, l23;
    h01.x = h[0]; h01.y = h[1]; h23.x = h[2]; h23.y = h[3];
    l01.x = l[0]; l01.y = l[1]; l23.x = l[2]; l23.y = l[3];
    __nv_bfloat162* p0 = (__nv_bfloat162*)(O + (size_t)m * KBIG + k4);
    __nv_bfloat162* p1 = (__nv_bfloat162*)(O + (size_t)m * KBIG + DMODEL + k4);
    __nv_bfloat162* p2 = (__nv_bfloat162*)(O + (size_t)m * KBIG + 2 * DMODEL + k4);
    p0[0] = h01; p0[1] = h23;      // hi
    p1[0] = l01; p1[1] = l23;      // lo
    p2[0] = h01; p2[1] = h23;      // hi
}

__global__ __launch_bounds__(256) void cvt_w(const float* __restrict__ W,
                                             __nv_bfloat16* __restrict__ O)
{
    __shared__ float t[32][33];
    int n0 = blockIdx.x * 32, k0 = blockIdx.y * 32;
    int tx = threadIdx.x, ty = threadIdx.y;
#pragma unroll
    for (int i = 0; i < 4; i++)
        t[ty + 8 * i][tx] = W[(size_t)(k0 + ty + 8 * i) * DMODEL + n0 + tx];
    __syncthreads();
#pragma unroll
    for (int i = 0; i < 4; i++) {
        int n = n0 + ty + 8 * i, k = k0 + tx;
        float v = t[tx][ty + 8 * i];
        __nv_bfloat16 h = __float2bfloat16(v);
        __nv_bfloat16 l = __float2bfloat16(v - __bfloat162float(h));
        O[(size_t)n * KBIG + k]              = h;
        O[(size_t)n * KBIG + DMODEL + k]     = h;
        O[(size_t)n * KBIG + 2 * DMODEL + k] = l;
    }
}

// fp32 [b*S+s][h*64+d] -> bf16 hi/lo [bh][s][64]
__global__ __launch_bounds__(256) void cvt_head(const float* __restrict__ X,
                                                __nv_bfloat16* __restrict__ Oh,
                                                __nv_bfloat16* __restrict__ Ol)
{
    int idx = blockIdx.x * 256 + threadIdx.x;
    int m   = idx >> 8;                       // 0..4095
    int col = (idx & 255) << 2;               // 0..1020
    int h   = col >> 6, d = col & 63;
    int b   = m >> 11, s = m & 2047;
    float4 v = *(const float4*)(X + (size_t)m * DMODEL + col);
    float f[4] = {v.x, v.y, v.z, v.w};
    __nv_bfloat16 hh[4], ll[4];
#pragma unroll
    for (int i = 0; i < 4; i++) {
        hh[i] = __float2bfloat16(f[i]);
        ll[i] = __float2bfloat16(f[i] - __bfloat162float(hh[i]));
    }
    size_t dst = ((size_t)(b * NHEAD + h) * S_LEN + s) * HDIM + d;
    __nv_bfloat162 a, c;
    a.x = hh[0]; a.y = hh[1]; c.x = hh[2]; c.y = hh[3];
    ((__nv_bfloat162*)(Oh + dst))[0] = a; ((__nv_bfloat162*)(Oh + dst))[1] = c;
    a.x = ll[0]; a.y = ll[1]; c.x = ll[2]; c.y = ll[3];
    ((__nv_bfloat162*)(Ol + dst))[0] = a; ((__nv_bfloat162*)(Ol + dst))[1] = c;
}

// V fp32 [b*S+s][h*64+d] -> transposed bf16 hi/lo [bh][d][s]
__global__ __launch_bounds__(256) void cvt_vt(const float* __restrict__ V,
                                              __nv_bfloat16* __restrict__ Oh,
                                              __nv_bfloat16* __restrict__ Ol)
{
    __shared__ float t[64][65];
    const int tid = threadIdx.x;
    const int s0  = blockIdx.x * 64;
    const int bh  = blockIdx.y;
    const int b   = bh >> 4, h = bh & 15;
#pragma unroll
    for (int i = 0; i < 16; i++) {
        int u = tid + i * 256;
        int s = u >> 6, d = u & 63;
        t[s][d] = V[((size_t)(b * S_LEN) + s0 + s) * DMODEL + h * 64 + d];
    }
    __syncthreads();
    const int d  = tid >> 2;
    const int jg = tid & 3;
    __nv_bfloat16 hv[16], lv[16];
#pragma unroll
    for (int jj = 0; jj < 16; jj++) {
        float v = t[jg * 16 + jj][d];
        hv[jj] = __float2bfloat16(v);
        lv[jj] = __float2bfloat16(v - __bfloat162float(hv[jj]));
    }
    size_t dst = ((size_t)bh * HDIM + d) * S_LEN + s0 + jg * 16;
    ((uint4*)(Oh + dst))[0] = ((uint4*)hv)[0];
    ((uint4*)(Oh + dst))[1] = ((uint4*)hv)[1];
    ((uint4*)(Ol + dst))[0] = ((uint4*)lv)[0];
    ((uint4*)(Ol + dst))[1] = ((uint4*)lv)[1];
}

// ---------------- bf16 HMMA GEMM (verified R8) ----------------
__global__ __launch_bounds__(256) void gemm_mma(
    const __nv_bfloat16* __restrict__ A,
    const __nv_bfloat16* __restrict__ B0, const __nv_bfloat16* __restrict__ B1,
    const __nv_bfloat16* __restrict__ B2,
    float* C0, float* C1, float* C2,
    const float* __restrict__ bias)
{
    extern __shared__ __align__(1024) unsigned char dsm[];

    const __nv_bfloat16* Bt = (blockIdx.z == 0) ? B0 : (blockIdx.z == 1) ? B1 : B2;
    float* C                = (blockIdx.z == 0) ? C0 : (blockIdx.z == 1) ? C1 : C2;

    const int tid  = threadIdx.x;
    const int wid  = tid >> 5;
    const int lane = tid & 31;
    const int bm   = blockIdx.y, bn = blockIdx.x;
    const int wm   = (wid & 1) * 64;
    const int wn   = (wid >> 1) * 32;

    const uint32_t s0 = smem_u32(dsm);
    const uint32_t sA = (s0 + 1023) & ~1023u;
    const uint32_t sB = sA + 32768;

    const int row0 = tid >> 3;
    const int seg  = tid & 7;
    const uint32_t swz = (uint32_t)((seg ^ (row0 & 7)) << 4);
    const __nv_bfloat16* aG = A  + (size_t)(bm * 128 + row0) * KBIG + seg * 8;
    const __nv_bfloat16* bG = Bt + (size_t)(bn * 128 + row0) * KBIG + seg * 8;
    const uint32_t stA = sA + row0 * 128 + swz;
    const uint32_t stB = sB + row0 * 128 + swz;

    uint32_t aBase[4], bBase[4], aMask[4], bMask[4];
#pragma unroll
    for (int mi = 0; mi < 4; mi++) {
        int r = wm + mi * 16 + (lane & 15);
        aBase[mi] = sA + r * 128;
        aMask[mi] = r & 7;
    }
#pragma unroll
    for (int ni = 0; ni < 4; ni++) {
        int r = wn + ni * 8 + (lane & 7);
        bBase[ni] = sB + r * 128;
        bMask[ni] = r & 7;
    }
    const uint32_t kselA = (lane >> 4);
    const uint32_t kselB = (lane >> 3) & 1;

    float acc[4][4][4];
#pragma unroll
    for (int mi = 0; mi < 4; mi++)
#pragma unroll
        for (int ni = 0; ni < 4; ni++)
#pragma unroll
            for (int r = 0; r < 4; r++) acc[mi][ni][r] = 0.0f;

    auto load_chunk = [&](int c, int buf) {
        const uint32_t bo = (uint32_t)buf * 16384;
        const __nv_bfloat16* ap = aG + c * 64;
        const __nv_bfloat16* bp = bG + c * 64;
#pragma unroll
        for (int i = 0; i < 4; i++) {
            cp_async16(stA + bo + i * 4096, ap + (size_t)i * 32 * KBIG);
            cp_async16(stB + bo + i * 4096, bp + (size_t)i * 32 * KBIG);
        }
        cp_commit();
    };

    load_chunk(0, 0);
    int buf = 0;
    for (int c = 0; c < KCH; c++) {
        cp_wait0();
        __syncthreads();
        if (c + 1 < KCH) load_chunk(c + 1, buf ^ 1);
        const uint32_t bo = (uint32_t)buf * 16384;
#pragma unroll
        for (int ks = 0; ks < 4; ks++) {
            uint32_t a[4][4], b[4][2];
#pragma unroll
            for (int mi = 0; mi < 4; mi++) {
                uint32_t u = (uint32_t)(ks * 2) + kselA;
                ldm_x4(a[mi][0], a[mi][1], a[mi][2], a[mi][3],
                       aBase[mi] + bo + ((u ^ aMask[mi]) << 4));
            }
#pragma unroll
            for (int ni = 0; ni < 4; ni++) {
                uint32_t u = (uint32_t)(ks * 2) + kselB;
                ldm_x2(b[ni][0], b[ni][1],
                       bBase[ni] + bo + ((u ^ bMask[ni]) << 4));
            }
#pragma unroll
            for (int mi = 0; mi < 4; mi++)
#pragma unroll
                for (int ni = 0; ni < 4; ni++)
                    mma_bf16(acc[mi][ni], a[mi], b[ni]);
        }
        buf ^= 1;
    }

    const int rbase = bm * 128 + wm + (lane >> 2);
    const int cbase = bn * 128 + wn + (lane & 3) * 2;
#pragma unroll
    for (int mi = 0; mi < 4; mi++) {
#pragma unroll
        for (int ni = 0; ni < 4; ni++) {
            const int col = cbase + ni * 8;
            float b0 = 0.0f, b1 = 0.0f;
            if (bias != nullptr) { b0 = bias[col]; b1 = bias[col + 1]; }
            float2 v01, v23;
            v01.x = acc[mi][ni][0] + b0; v01.y = acc[mi][ni][1] + b1;
            v23.x = acc[mi][ni][2] + b0; v23.y = acc[mi][ni][3] + b1;
            *(float2*)(C + (size_t)(rbase + mi * 16)     * DMODEL + col) = v01;
            *(float2*)(C + (size_t)(rbase + mi * 16 + 8) * DMODEL + col) = v23;
        }
    }
}

// ---------------- HMMA flash attention (causal, unscaled, bf16 hi/lo 3-pass) ----
// grid (16, 32): CTA = 128 q-rows; 8 warps x 16 rows. k-tiles of 64.
// smem: Qh,Ql (16KB ea) + 2 stages x {Kh,Kl,Vth,Vtl} (8KB ea) = 96KB.
__global__ __launch_bounds__(256, 2) void flash_mma(
    const __nv_bfloat16* __restrict__ Qh, const __nv_bfloat16* __restrict__ Ql,
    const __nv_bfloat16* __restrict__ Kh, const __nv_bfloat16* __restrict__ Kl,
    const __nv_bfloat16* __restrict__ Vth, const __nv_bfloat16* __restrict__ Vtl,
    float* __restrict__ Ctx)
{
    extern __shared__ __align__(1024) unsigned char dsm[];
    const int tid  = threadIdx.x;
    const int wid  = tid >> 5;
    const int lane = tid & 31;
    const int qt   = (int)gridDim.x - 1 - (int)blockIdx.x;   // big tiles first
    const int bh   = blockIdx.y;
    const int b    = bh >> 4, h = bh & 15;

    const uint32_t s0   = smem_u32(dsm);
    const uint32_t sQh  = (s0 + 1023) & ~1023u;
    const uint32_t sQl  = sQh + 16384;
    const uint32_t sStg = sQh + 32768;          // 2 x 32768

    // ---- load Q tile (128 rows x 128B) hi+lo, swizzled ----
    {
        const __nv_bfloat16* qh = Qh + ((size_t)bh * S_LEN + qt * 128) * HDIM;
        const __nv_bfloat16* ql = Ql + ((size_t)bh * S_LEN + qt * 128) * HDIM;
#pragma unroll
        for (int i = 0; i < 4; i++) {
            int u   = tid + i * 256;            // 0..1023
            int row = u >> 3, seg = u & 7;
            uint32_t off = row * 128 + (((uint32_t)(seg ^ (row & 7))) << 4);
            *(uint4*)(dsm + (sQh - s0) + off) = *(const uint4*)(qh + (size_t)row * HDIM + seg * 8);
            *(uint4*)(dsm + (sQl - s0) + off) = *(const uint4*)(ql + (size_t)row * HDIM + seg * 8);
        }
    }

    // ---- producer: K/V tile prefetch ----
    const int prow = tid >> 3;                  // 0..31
    const int pseg = tid & 7;
    const uint32_t psw = ((uint32_t)(pseg ^ (prow & 7))) << 4;
    auto prefetch = [&](int kt, int bufi) {
        const uint32_t so = sStg + (uint32_t)bufi * 32768;
        const __nv_bfloat16* khG = Kh  + ((size_t)bh * S_LEN + kt * 64) * HDIM;
        const __nv_bfloat16* klG = Kl  + ((size_t)bh * S_LEN + kt * 64) * HDIM;
        const __nv_bfloat16* vhG = Vth + ((size_t)bh * HDIM) * S_LEN + kt * 64;
        const __nv_bfloat16* vlG = Vtl + ((size_t)bh * HDIM) * S_LEN + kt * 64;
#pragma unroll
        for (int i = 0; i < 2; i++) {
            int row = prow + i * 32;
            uint32_t off = row * 128 + psw;
            cp_async16(so +     0 + off, khG + (size_t)row * HDIM  + pseg * 8);
            cp_async16(so +  8192 + off, klG + (size_t)row * HDIM  + pseg * 8);
            cp_async16(so + 16384 + off, vhG + (size_t)row * S_LEN + pseg * 8);
            cp_async16(so + 24576 + off, vlG + (size_t)row * S_LEN + pseg * 8);
        }
        cp_commit();
    };

    // ---- consumer addressing ----
    const int qrow      = wid * 16 + (lane & 15);
    const uint32_t qOff = (uint32_t)qrow * 128;
    const uint32_t qMsk = qrow & 7;
    const uint32_t kselA = lane >> 4;
    const uint32_t kselB = (lane >> 3) & 1;
    const int brow = lane & 7;

    float o[8][4];
#pragma unroll
    for (int n = 0; n < 8; n++)
#pragma unroll
        for (int r = 0; r < 4; r++) o[n][r] = 0.0f;
    float m0 = -1.0e30f, m1 = -1.0e30f, l0 = 0.0f, l1 = 0.0f;

    const int ktn = 2 * qt + 2;
    prefetch(0, 0);
    int buf = 0;
    for (int kt = 0; kt < ktn; kt++) {
        cp_wait0();
        __syncthreads();
        if (kt + 1 < ktn) prefetch(kt + 1, buf ^ 1);
        const uint32_t so = sStg + (uint32_t)buf * 32768;
        buf ^= 1;

        // fully masked for this warp? (still did barrier work above)
        if (kt * 64 > qt * 128 + wid * 16 + 15) continue;

        // ---- S = Q K^T (3-pass hi/lo) ----
        float s[8][4];
#pragma unroll
        for (int n = 0; n < 8; n++)
#pragma unroll
            for (int r = 0; r < 4; r++) s[n][r] = 0.0f;
#pragma unroll
        for (int ks = 0; ks < 4; ks++) {
            uint32_t aH[4], aL[4];
            uint32_t ua = (uint32_t)(ks * 2) + kselA;
            ldm_x4(aH[0], aH[1], aH[2], aH[3], sQh + qOff + (((ua ^ qMsk)) << 4));
            ldm_x4(aL[0], aL[1], aL[2], aL[3], sQl + qOff + (((ua ^ qMsk)) << 4));
            uint32_t ub = (uint32_t)(ks * 2) + kselB;
#pragma unroll
            for (int n = 0; n < 8; n++) {
                int r = n * 8 + brow;
                uint32_t off = (uint32_t)r * 128 + (((ub ^ (uint32_t)(r & 7))) << 4);
                uint32_t bh2[2], bl2[2];
                ldm_x2(bh2[0], bh2[1], so + 0    + off);
                ldm_x2(bl2[0], bl2[1], so + 8192 + off);
                mma_bf16(s[n], aH, bh2);
                mma_bf16(s[n], aL, bh2);
                mma_bf16(s[n], aH, bl2);
            }
        }

        // ---- causal mask (only possible in last two tiles) ----
        const int rg0 = qt * 128 + wid * 16 + (lane >> 2);
        if (kt * 64 + 63 > rg0) {
#pragma unroll
            for (int n = 0; n < 8; n++) {
                int cg = kt * 64 + n * 8 + (lane & 3) * 2;
                if (cg     > rg0)     s[n][0] = -1.0e30f;
                if (cg + 1 > rg0)     s[n][1] = -1.0e30f;
                if (cg     > rg0 + 8) s[n][2] = -1.0e30f;
                if (cg + 1 > rg0 + 8) s[n][3] = -1.0e30f;
            }
        }

        // ---- online softmax (rows: rg0, rg0+8 per thread) ----
        float mx0 = -1.0e30f, mx1 = -1.0e30f;
#pragma unroll
        for (int n = 0; n < 8; n++) {
            mx0 = fmaxf(mx0, fmaxf(s[n][0], s[n][1]));
            mx1 = fmaxf(mx1, fmaxf(s[n][2], s[n][3]));
        }
        mx0 = fmaxf(mx0, __shfl_xor_sync(0xffffffffu, mx0, 1));
        mx0 = fmaxf(mx0, __shfl_xor_sync(0xffffffffu, mx0, 2));
        mx1 = fmaxf(mx1, __shfl_xor_sync(0xffffffffu, mx1, 1));
        mx1 = fmaxf(mx1, __shfl_xor_sync(0xffffffffu, mx1, 2));
        const float mn0 = fmaxf(m0, mx0), mn1 = fmaxf(m1, mx1);
        const float sc0 = __expf(m0 - mn0), sc1 = __expf(m1 - mn1);
        float rs0 = 0.0f, rs1 = 0.0f;
#pragma unroll
        for (int n = 0; n < 8; n++) {
            s[n][0] = __expf(s[n][0] - mn0);
            s[n][1] = __expf(s[n][1] - mn0);
            s[n][2] = __expf(s[n][2] - mn1);
            s[n][3] = __expf(s[n][3] - mn1);
            rs0 += s[n][0] + s[n][1];
            rs1 += s[n][2] + s[n][3];
        }
        rs0 += __shfl_xor_sync(0xffffffffu, rs0, 1);
        rs0 += __shfl_xor_sync(0xffffffffu, rs0, 2);
        rs1 += __shfl_xor_sync(0xffffffffu, rs1, 1);
        rs1 += __shfl_xor_sync(0xffffffffu, rs1, 2);
        m0 = mn0; m1 = mn1;
        l0 = l0 * sc0 + rs0; l1 = l1 * sc1 + rs1;
#pragma unroll
        for (int n = 0; n < 8; n++) {
            o[n][0] *= sc0; o[n][1] *= sc0;
            o[n][2] *= sc1; o[n][3] *= sc1;
        }

        // ---- P fragments (hi + lo), FA2 accumulator->A mapping ----
        uint32_t pH[4][4], pL[4][4];
#pragma unroll
        for (int f = 0; f < 4; f++) {
            const int n0i = 2 * f, n1i = 2 * f + 1;
            pH[f][0] = packbf2(s[n0i][0], s[n0i][1]);
            pH[f][1] = packbf2(s[n0i][2], s[n0i][3]);
            pH[f][2] = packbf2(s[n1i][0], s[n1i][1]);
            pH[f][3] = packbf2(s[n1i][2], s[n1i][3]);
            pL[f][0] = packbf2(s[n0i][0] - bf16rt(s[n0i][0]), s[n0i][1] - bf16rt(s[n0i][1]));
            pL[f][1] = packbf2(s[n0i][2] - bf16rt(s[n0i][2]), s[n0i][3] - bf16rt(s[n0i][3]));
            pL[f][2] = packbf2(s[n1i][0] - bf16rt(s[n1i][0]), s[n1i][1] - bf16rt(s[n1i][1]));
            pL[f][3] = packbf2(s[n1i][2] - bf16rt(s[n1i][2]), s[n1i][3] - bf16rt(s[n1i][3]));
        }

        // ---- O += P V (3-pass) ----
#pragma unroll
        for (int f = 0; f < 4; f++) {
            uint32_t ub = (uint32_t)(f * 2) + kselB;
#pragma unroll
            for (int n = 0; n < 8; n++) {
                int r = n * 8 + brow;
                uint32_t off = (uint32_t)r * 128 + (((ub ^ (uint32_t)(r & 7))) << 4);
                uint32_t bvh[2], bvl[2];
                ldm_x2(bvh[0], bvh[1], so + 16384 + off);
                ldm_x2(bvl[0], bvl[1], so + 24576 + off);
                mma_bf16(o[n], pH[f], bvh);
                mma_bf16(o[n], pL[f], bvh);
                mma_bf16(o[n], pH[f], bvl);
            }
        }
    }

    // ---- normalize + store ctx fp32 [b*S+s][h*64+c] ----
    const float inv0 = 1.0f / l0, inv1 = 1.0f / l1;
    const int r0g = qt * 128 + wid * 16 + (lane >> 2);
#pragma unroll
    for (int n = 0; n < 8; n++) {
        const int col = h * 64 + n * 8 + (lane & 3) * 2;
        float2 v01, v23;
        v01.x = o[n][0] * inv0; v01.y = o[n][1] * inv0;
        v23.x = o[n][2] * inv1; v23.y = o[n][3] * inv1;
        *(float2*)(Ctx + ((size_t)(b * S_LEN) + r0g)     * DMODEL + col) = v01;
        *(float2*)(Ctx + ((size_t)(b * S_LEN) + r0g + 8) * DMODEL + col) = v23;
    }
}

// ---------------- launcher ----------------
extern "C" void kernel_launch(void* const* d_in, const int* in_sizes, int n_in,
                              void* d_out, int out_size)
{
    const float* X  = (const float*)d_in[0];
    const float* Wq = (const float*)d_in[1];
    const float* Wk = (const float*)d_in[2];
    const float* Wv = (const float*)d_in[3];
    const float* Wo = (const float*)d_in[4];
    const float* bo = (const float*)d_in[5];
    float* out = (float*)d_out;

    __nv_bfloat16 *xbig, *cbig, *wqb, *wkb, *wvb, *wob;
    __nv_bfloat16 *qh, *ql, *kh, *kl, *vth, *vtl;
    float *q, *k, *v, *ctx;
    cudaGetSymbolAddress((void**)&xbig, g_xbig);
    cudaGetSymbolAddress((void**)&cbig, g_cbig);
    cudaGetSymbolAddress((void**)&wqb,  g_wqb);
    cudaGetSymbolAddress((void**)&wkb,  g_wkb);
    cudaGetSymbolAddress((void**)&wvb,  g_wvb);
    cudaGetSymbolAddress((void**)&wob,  g_wob);
    cudaGetSymbolAddress((void**)&q,    g_q);
    cudaGetSymbolAddress((void**)&k,    g_k);
    cudaGetSymbolAddress((void**)&v,    g_v);
    cudaGetSymbolAddress((void**)&ctx,  g_ctx);
    cudaGetSymbolAddress((void**)&qh,   g_qh);
    cudaGetSymbolAddress((void**)&ql,   g_ql);
    cudaGetSymbolAddress((void**)&kh,   g_kh);
    cudaGetSymbolAddress((void**)&kl,   g_kl);
    cudaGetSymbolAddress((void**)&vth,  g_vth);
    cudaGetSymbolAddress((void**)&vtl,  g_vtl);

    const int SMEM_GEMM = 65536 + 1024;
    const int SMEM_FA   = 98304 + 1024;
    cudaFuncSetAttribute(gemm_mma, cudaFuncAttributeMaxDynamicSharedMemorySize, SMEM_GEMM);
    cudaFuncSetAttribute(flash_mma, cudaFuncAttributeMaxDynamicSharedMemorySize, SMEM_FA);

    // conversions
    cvt_x<<<MROWS * DMODEL / (256 * 4), 256>>>(X, xbig);
    dim3 wgrid(DMODEL / 32, DMODEL / 32);
    cvt_w<<<wgrid, dim3(32, 8)>>>(Wq, wqb);
    cvt_w<<<wgrid, dim3(32, 8)>>>(Wk, wkb);
    cvt_w<<<wgrid, dim3(32, 8)>>>(Wv, wvb);
    cvt_w<<<wgrid, dim3(32, 8)>>>(Wo, wob);

    // QKV projection (HMMA)
    gemm_mma<<<dim3(DMODEL / 128, MROWS / 128, 3), 256, SMEM_GEMM>>>(
        xbig, wqb, wkb, wvb, q, k, v, nullptr);

    // attention operand prep
    const int cg = MROWS * DMODEL / (256 * 4);
    cvt_head<<<cg, 256>>>(q, qh, ql);
    cvt_head<<<cg, 256>>>(k, kh, kl);
    cvt_vt<<<dim3(S_LEN / 64, NBH), 256>>>(v, vth, vtl);

    // flash attention (HMMA)
    flash_mma<<<dim3(S_LEN / 128, NBH), 256, SMEM_FA>>>(qh, ql, kh, kl, vth, vtl, ctx);

    // output projection
    cvt_x<<<MROWS * DMODEL / (256 * 4), 256>>>(ctx, cbig);
    gemm_mma<<<dim3(DMODEL / 128, MROWS / 128, 1), 256, SMEM_GEMM>>>(
        cbig, wob, wob, wob, out, out, out, bo);
}